// round 7
// baseline (speedup 1.0000x reference)
#include <cuda_runtime.h>
#include <cuda_fp16.h>
#include <cstdint>

#define TB_ 131072
#define B_  32

// ---------------- device scratch (no allocation allowed) ----------------
__device__ float  g_hbre[B_ * 512];            // [b][nt*128 + hl*4 + q]
__device__ uint2  g_wfrag[4 * 16 * 8 * 32];    // [nt][nf][ks][lane] -> {b0,b1}
// fp16 A, pre-swizzled, in 16KB blocks: [mt*2+half][row(128)][chunk^(row&7)](16B)
__device__ __half g_ah[(size_t)TB_ * 128];

// ---------------- helpers ----------------
__device__ __forceinline__ uint32_t smem_u32(const void* p) {
    uint32_t a;
    asm("{ .reg .u64 t; cvta.to.shared.u64 t, %1; cvt.u32.u64 %0, t; }" : "=r"(a) : "l"(p));
    return a;
}
__device__ __forceinline__ float tanh_ap(float x) {
    float y; asm("tanh.approx.f32 %0, %1;" : "=f"(y) : "f"(x)); return y;
}
__device__ __forceinline__ float sig_ap(float x) { return fmaf(tanh_ap(x * 0.5f), 0.5f, 0.5f); }

// ---------------- fused prep kernel ----------------
__global__ void prep_all(const float* __restrict__ input, const float* __restrict__ h0,
                         const float* __restrict__ W_hh, const float* __restrict__ b_ih,
                         const float* __restrict__ b_hh, const float* __restrict__ W_ih) {
    const int bx = blockIdx.x, tid = threadIdx.x;
    if (bx < 64) {
        int idx = bx * 256 + tid;                 // Hb, reordered
        int b = idx & 31, g = idx >> 5;
        const float4* wv = (const float4*)(W_hh + g * 128);
        const float4* hv = (const float4*)(h0 + b * 128);
        float s0 = b_ih[g] + b_hh[g], s1 = 0.f, s2 = 0.f, s3 = 0.f;
#pragma unroll
        for (int k = 0; k < 32; k++) {
            float4 w = wv[k], h = hv[k];
            s0 += w.x * h.x; s1 += w.y * h.y; s2 += w.z * h.z; s3 += w.w * h.w;
        }
        float s = (s0 + s1) + (s2 + s3);
        int q = g >> 7, rest = g & 127, nt = rest >> 5, hl = rest & 31;
        g_hbre[b * 512 + nt * 128 + hl * 4 + q] = s;
    } else if (bx < 128) {
        // W_ih -> fp16 B-fragment-major (m16n8k16 B frag)
        int idx = (bx - 64) * 256 + tid;
        int l = idx & 31, ks = (idx >> 5) & 7, nf = (idx >> 8) & 15, nt = idx >> 12;
        int t = l & 3, gq = l >> 2;
        int n = nf * 8 + gq;
        int k0 = ks * 16 + t * 2;
        int g = (n & 3) * 128 + nt * 32 + (n >> 2);
        const float* wr = W_ih + g * 128;
        __half2 b0 = __floats2half2_rn(wr[k0], wr[k0 + 1]);
        __half2 b1 = __floats2half2_rn(wr[k0 + 8], wr[k0 + 9]);
        g_wfrag[idx] = make_uint2(*(uint32_t*)&b0, *(uint32_t*)&b1);
    } else {
        // input fp32 -> fp16, swizzled into 16KB [tile][half] blocks
        int ci = (bx - 128) * 256 + tid;          // 0 .. TB_*16-1 (16B chunks)
        int row_g = ci >> 4, c = ci & 15;
        const float4* ip = (const float4*)input;
        float4 v0 = ip[(size_t)row_g * 32 + c * 2];
        float4 v1 = ip[(size_t)row_g * 32 + c * 2 + 1];
        __half2 h0p = __floats2half2_rn(v0.x, v0.y);
        __half2 h1p = __floats2half2_rn(v0.z, v0.w);
        __half2 h2p = __floats2half2_rn(v1.x, v1.y);
        __half2 h3p = __floats2half2_rn(v1.z, v1.w);
        size_t off = ((size_t)((row_g >> 7) * 2 + (c >> 3)) << 14)
                   + (size_t)(row_g & 127) * 128
                   + (uint32_t)(((c & 7) ^ (row_g & 7)) << 4);
        uint4 pk = make_uint4(*(uint32_t*)&h0p, *(uint32_t*)&h1p, *(uint32_t*)&h2p, *(uint32_t*)&h3p);
        *(uint4*)((char*)g_ah + off) = pk;
    }
}

// ---------------- main kernel ----------------
#define SMEM_A0  0                 // 16384 : A half-tile buf 0
#define SMEM_A1  16384             // 16384 : A half-tile buf 1
#define SMEM_B   32768             // 32768 : B frags (uint2 x 4096)
#define SMEM_HS  65536             // 16384 : h stage [128][32] f32, chunk-swizzled
#define SMEM_HB  81920             // 16896 : HBs [32][132] f32
#define SMEM_C0  98816             // 4224  : c0   [32][33]
#define SMEM_NZ  103040            // 4224  : noise[32][33]
#define SMEM_TOT 107264            // 104.75 KB

__global__ __launch_bounds__(256, 2)
void lstm_mma(const float* __restrict__ c0, const float* __restrict__ noise,
              float* __restrict__ out) {
    extern __shared__ char sm[];
    uint2* Bs  = (uint2*)(sm + SMEM_B);
    float* Hs  = (float*)(sm + SMEM_HS);
    float* HBs = (float*)(sm + SMEM_HB);
    float* C0s = (float*)(sm + SMEM_C0);
    float* NZs = (float*)(sm + SMEM_NZ);

    const int tid = threadIdx.x;
    const int wid = tid >> 5, lane = tid & 31;
    const int nt = blockIdx.x & 3, grp = blockIdx.x >> 2;
    const int wm = wid & 1, wn = wid >> 1;            // 2m x 4n warp grid
    const uint32_t smb = smem_u32(sm);
    const int gt2 = grp * 8;                          // first g_ah block of this CTA

    // ---- prologue: prefetch steps 0 and 1 ----
    {
        const char* gp0 = (const char*)g_ah + ((size_t)gt2 << 14) + tid * 16;
        const char* gp1 = gp0 + 16384;
        uint32_t d0 = smb + SMEM_A0 + tid * 16, d1 = smb + SMEM_A1 + tid * 16;
#pragma unroll
        for (int j = 0; j < 4; j++)
            asm volatile("cp.async.cg.shared.global [%0],[%1],16;" :: "r"(d0 + j * 4096), "l"(gp0 + j * 4096));
        asm volatile("cp.async.commit_group;");
#pragma unroll
        for (int j = 0; j < 4; j++)
            asm volatile("cp.async.cg.shared.global [%0],[%1],16;" :: "r"(d1 + j * 4096), "l"(gp1 + j * 4096));
        asm volatile("cp.async.commit_group;");
    }

    // ---- stage B fragments, HB, c0, noise (once per CTA) ----
    {
        const uint2* src = g_wfrag + nt * 4096;
        for (int i = tid; i < 4096; i += 256) Bs[i] = src[i];
        for (int i = tid; i < 4096; i += 256) {
            int b = i >> 7, c = i & 127;
            HBs[b * 132 + c] = g_hbre[b * 512 + nt * 128 + c];
        }
        for (int i = tid; i < 1024; i += 256) {
            int b = i >> 5, hl = i & 31;
            C0s[b * 33 + hl] = c0[b * 128 + nt * 32 + hl];
            NZs[b * 33 + hl] = noise[b * 128 + nt * 32 + hl];
        }
    }

    const int arow = lane & 15;                       // ldmatrix row-in-frag
    const int ahi  = lane >> 4;                       // 0/1: chunk select
    const int aswz = arow & 7;                        // per-lane chunk XOR
    const int t = lane & 3, g = lane >> 2, odd = lane & 1;

    for (int tile = 0; tile < 4; tile++) {
        const long r0 = (long)(grp * 4 + tile) * 128;
        float acc[4][4][4];
#pragma unroll
        for (int mf = 0; mf < 4; mf++)
#pragma unroll
            for (int nf = 0; nf < 4; nf++)
#pragma unroll
                for (int r = 0; r < 4; r++) acc[mf][nf][r] = 0.f;

#pragma unroll
        for (int half = 0; half < 2; half++) {
            const int s = tile * 2 + half;
            const uint32_t Aoff = (s & 1) ? SMEM_A1 : SMEM_A0;

            asm volatile("cp.async.wait_group 1;" ::: "memory");
            __syncthreads();                           // buf[s&1] ready for all warps

            // ---- MMA on this K=64 half ----
#pragma unroll
            for (int ksl = 0; ksl < 4; ksl++) {
                const int ks = half * 4 + ksl;
                uint2 bfr[4];
#pragma unroll
                for (int nf = 0; nf < 4; nf++)
                    bfr[nf] = Bs[((wn * 4 + nf) * 8 + ks) * 32 + lane];
#pragma unroll
                for (int mf = 0; mf < 4; mf++) {
                    uint32_t row = (uint32_t)(wm * 64 + mf * 16 + arow);
                    uint32_t chn = (uint32_t)((ksl * 2 + ahi) ^ aswz);
                    uint32_t addr = smb + Aoff + row * 128 + chn * 16;
                    uint32_t a0, a1, a2, a3;
                    asm volatile("ldmatrix.sync.aligned.m8n8.x4.shared.b16 {%0,%1,%2,%3}, [%4];"
                                 : "=r"(a0), "=r"(a1), "=r"(a2), "=r"(a3) : "r"(addr));
#pragma unroll
                    for (int nf = 0; nf < 4; nf++) {
                        asm volatile(
                            "mma.sync.aligned.m16n8k16.row.col.f32.f16.f16.f32 "
                            "{%0,%1,%2,%3}, {%4,%5,%6,%7}, {%8,%9}, {%0,%1,%2,%3};"
                            : "+f"(acc[mf][nf][0]), "+f"(acc[mf][nf][1]),
                              "+f"(acc[mf][nf][2]), "+f"(acc[mf][nf][3])
                            : "r"(a0), "r"(a1), "r"(a2), "r"(a3),
                              "r"(bfr[nf].x), "r"(bfr[nf].y));
                    }
                }
            }
            __syncthreads();                           // all reads of buf[s&1] done

            // ---- prefetch step s+2 into buf[s&1] ----
            if (s + 2 < 8) {
                const char* gp = (const char*)g_ah + ((size_t)(gt2 + s + 2) << 14) + tid * 16;
                uint32_t sd = smb + Aoff + tid * 16;
#pragma unroll
                for (int j = 0; j < 4; j++)
                    asm volatile("cp.async.cg.shared.global [%0],[%1],16;" :: "r"(sd + j * 4096), "l"(gp + j * 4096));
            }
            asm volatile("cp.async.commit_group;");    // dummy group when none issued
        }

        // ---- fused LSTM epilogue ----
#pragma unroll
        for (int mf = 0; mf < 4; mf++) {
#pragma unroll
            for (int nf = 0; nf < 4; nf++) {
                float c0r = acc[mf][nf][0], c1r = acc[mf][nf][1];
                float c2r = acc[mf][nf][2], c3r = acc[mf][nf][3];
                float v0 = __shfl_xor_sync(0xffffffffu, c0r, 1);
                float v1 = __shfl_xor_sync(0xffffffffu, c1r, 1);
                float v2 = __shfl_xor_sync(0xffffffffu, c2r, 1);
                float v3 = __shfl_xor_sync(0xffffffffu, c3r, 1);
                float g0, g1, g2, g3;
                if (!odd) { g0 = c0r; g1 = c1r; g2 = v0; g3 = v1; }
                else      { g0 = v2;  g1 = v3;  g2 = c2r; g3 = c3r; }
                int row = wm * 64 + mf * 16 + g + (odd ? 8 : 0);
                int hl  = wn * 8 + nf * 2 + (t >> 1);
                int b   = row & 31;
                float4 hb = *(float4*)(HBs + b * 132 + hl * 4);
                float gi = g0 + hb.x, gf = g1 + hb.y, gg = g2 + hb.z, go = g3 + hb.w;
                float si = sig_ap(gi), sf = sig_ap(gf), so = sig_ap(go);
                float tg = tanh_ap(gg);
                float cc = sf * C0s[b * 33 + hl] + si * tg;
                float hv = so * tanh_ap(cc) + NZs[b * 33 + hl];
                Hs[row * 32 + (((hl >> 2) ^ (row & 7)) << 2) + (hl & 3)] = hv;
                long gr = r0 + row;
                if (gr >= (long)TB_ - 32) {            // last timestep rows
                    long base = (long)TB_ * 128 + (long)b * 128 + nt * 32 + hl;
                    out[base] = hv;                    // h_last
                    out[base + 32 * 128] = cc;         // c_last
                }
            }
        }
        __syncthreads();

        // ---- coalesced store of h tile ----
#pragma unroll
        for (int j = 0; j < 4; j++) {
            int i4 = tid + j * 256;
            int row = i4 >> 3, hq = i4 & 7;
            float4 hv = *(float4*)(Hs + row * 32 + ((hq ^ (row & 7)) << 2));
            *(float4*)(out + (r0 + row) * 128 + nt * 32 + hq * 4) = hv;
        }
        __syncthreads();                               // Hs free for next tile
    }
}

// ---------------- launch ----------------
extern "C" void kernel_launch(void* const* d_in, const int* in_sizes, int n_in,
                              void* d_out, int out_size) {
    const float* input = (const float*)d_in[0];
    const float* h0    = (const float*)d_in[1];
    const float* c0    = (const float*)d_in[2];
    const float* noise = (const float*)d_in[3];
    const float* W_ih  = (const float*)d_in[4];
    const float* W_hh  = (const float*)d_in[5];
    const float* b_ih  = (const float*)d_in[6];
    const float* b_hh  = (const float*)d_in[7];
    float* out = (float*)d_out;

    prep_all<<<128 + TB_ * 16 / 256, 256>>>(input, h0, W_hh, b_ih, b_hh, W_ih);

    cudaFuncSetAttribute(lstm_mma, cudaFuncAttributeMaxDynamicSharedMemorySize, SMEM_TOT);
    lstm_mma<<<1024, 256, SMEM_TOT>>>(c0, noise, out);
}

// round 8
// speedup vs baseline: 1.0179x; 1.0179x over previous
#include <cuda_runtime.h>
#include <cuda_fp16.h>
#include <cstdint>

#define TB_ 131072
#define B_  32

// ---------------- device scratch (no allocation allowed) ----------------
__device__ float g_hbre[B_ * 512];             // [b][nt*128 + hl*4 + q]
__device__ uint2 g_wfrag[4 * 16 * 8 * 32];     // [nt][nf][ks][lane] -> {b0,b1}
// A in fragment-major layout: [mt(1024)][ks(8)][rg(8)][lane(32)] -> uint4 {a0,a1,a2,a3}
__device__ uint4 g_afrag[1024 * 8 * 8 * 32];   // 33.5 MB

// ---------------- helpers ----------------
__device__ __forceinline__ float tanh_ap(float x) {
    float y; asm("tanh.approx.f32 %0, %1;" : "=f"(y) : "f"(x)); return y;
}
__device__ __forceinline__ float sig_ap(float x) { return fmaf(tanh_ap(x * 0.5f), 0.5f, 0.5f); }

// ---------------- fused prep kernel ----------------
// blocks [0,64):    Hb = h0 @ W_hh^T + b_ih + b_hh (reordered)
// blocks [64,128):  W_ih -> fp16 B-fragment-major
// blocks [128,8320): input fp32 -> fp16 A-fragment-major
__global__ void prep_all(const float* __restrict__ input, const float* __restrict__ h0,
                         const float* __restrict__ W_hh, const float* __restrict__ b_ih,
                         const float* __restrict__ b_hh, const float* __restrict__ W_ih) {
    const int bx = blockIdx.x, tid = threadIdx.x;
    if (bx < 64) {
        int idx = bx * 256 + tid;
        int b = idx & 31, g = idx >> 5;
        const float4* wv = (const float4*)(W_hh + g * 128);
        const float4* hv = (const float4*)(h0 + b * 128);
        float s0 = b_ih[g] + b_hh[g], s1 = 0.f, s2 = 0.f, s3 = 0.f;
#pragma unroll
        for (int k = 0; k < 32; k++) {
            float4 w = wv[k], h = hv[k];
            s0 += w.x * h.x; s1 += w.y * h.y; s2 += w.z * h.z; s3 += w.w * h.w;
        }
        float s = (s0 + s1) + (s2 + s3);
        int q = g >> 7, rest = g & 127, nt = rest >> 5, hl = rest & 31;
        g_hbre[b * 512 + nt * 128 + hl * 4 + q] = s;
    } else if (bx < 128) {
        // m16n8k16 B frag: b0={B[k0][n],B[k0+1][n]}, b1={B[k0+8][n],B[k0+9][n]}
        int idx = (bx - 64) * 256 + tid;
        int l = idx & 31, ks = (idx >> 5) & 7, nf = (idx >> 8) & 15, nt = idx >> 12;
        int t = l & 3, gq = l >> 2;
        int n = nf * 8 + gq;
        int k0 = ks * 16 + t * 2;
        int g = (n & 3) * 128 + nt * 32 + (n >> 2);
        const float* wr = W_ih + g * 128;
        __half2 b0 = __floats2half2_rn(wr[k0], wr[k0 + 1]);
        __half2 b1 = __floats2half2_rn(wr[k0 + 8], wr[k0 + 9]);
        g_wfrag[idx] = make_uint2(*(uint32_t*)&b0, *(uint32_t*)&b1);
    } else {
        // m16n8k16 A frag (row-major): a0={A[g][k0,k0+1]}, a1={A[g+8][k0,k0+1]},
        //                              a2={A[g][k0+8,k0+9]}, a3={A[g+8][k0+8,k0+9]}
        // with g = lane>>2 (+row base), k0 = ks*16 + (lane&3)*2
        int ci = (bx - 128) * 256 + tid;        // frag element linear index
        int lane = ci & 31;
        int rg   = (ci >> 5) & 7;
        int ks   = (ci >> 8) & 7;
        int mt   = ci >> 11;
        int g2 = lane >> 2, t2 = (lane & 3) * 2;
        const float* ip = input + ((size_t)mt * 128 + rg * 16 + g2) * 128 + ks * 16 + t2;
        float2 x00 = *(const float2*)(ip);
        float2 x10 = *(const float2*)(ip + 8 * 128);
        float2 x01 = *(const float2*)(ip + 8);
        float2 x11 = *(const float2*)(ip + 8 * 128 + 8);
        __half2 a0 = __floats2half2_rn(x00.x, x00.y);
        __half2 a1 = __floats2half2_rn(x10.x, x10.y);
        __half2 a2 = __floats2half2_rn(x01.x, x01.y);
        __half2 a3 = __floats2half2_rn(x11.x, x11.y);
        g_afrag[ci] = make_uint4(*(uint32_t*)&a0, *(uint32_t*)&a1,
                                 *(uint32_t*)&a2, *(uint32_t*)&a3);
    }
}

// ---------------- main kernel ----------------
#define SMEM_B   0                 // 32768 : B frags (uint2 x 4096)
#define SMEM_HB  32768             // 16896 : HBs [32][132] f32
#define SMEM_C0  49664             // 4224  : c0   [32][33]
#define SMEM_NZ  53888             // 4224  : noise[32][33]
#define SMEM_TOT 58112             // 56.75 KB -> 2 CTAs/SM

__global__ __launch_bounds__(256, 2)
void lstm_mma(const float* __restrict__ c0, const float* __restrict__ noise,
              float* __restrict__ out) {
    extern __shared__ char sm[];
    uint2* Bs  = (uint2*)(sm + SMEM_B);
    float* HBs = (float*)(sm + SMEM_HB);
    float* C0s = (float*)(sm + SMEM_C0);
    float* NZs = (float*)(sm + SMEM_NZ);

    const int tid = threadIdx.x;
    const int wid = tid >> 5, lane = tid & 31;
    const int nt = blockIdx.x & 3, grp = blockIdx.x >> 2;
    const int wm = wid & 1, wn = wid >> 1;            // 2m x 4n warp grid

    // ---- stage B fragments, HB, c0, noise (once per CTA) ----
    {
        const uint2* src = g_wfrag + nt * 4096;
        for (int i = tid; i < 4096; i += 256) Bs[i] = src[i];
        for (int i = tid; i < 4096; i += 256) {
            int b = i >> 7, c = i & 127;
            HBs[b * 132 + c] = g_hbre[b * 512 + nt * 128 + c];
        }
        for (int i = tid; i < 1024; i += 256) {
            int b = i >> 5, hl = i & 31;
            C0s[b * 33 + hl] = c0[b * 128 + nt * 32 + hl];
            NZs[b * 33 + hl] = noise[b * 128 + nt * 32 + hl];
        }
    }
    __syncthreads();                                   // only barrier in the kernel

    const int t = lane & 3, g = lane >> 2, odd = lane & 1;
    const int th = t >> 1;

    for (int tile = 0; tile < 4; tile++) {
        const int mt = grp * 4 + tile;
        const long r0 = (long)mt * 128;
        // A frag pointers: [mt][ks][rg = wm*4+mf][lane]
        const uint4* Ag = g_afrag + (((size_t)mt * 8) * 8 + wm * 4) * 32 + lane;

        float acc[4][4][4];
#pragma unroll
        for (int mf = 0; mf < 4; mf++)
#pragma unroll
            for (int nf = 0; nf < 4; nf++)
#pragma unroll
                for (int r = 0; r < 4; r++) acc[mf][nf][r] = 0.f;

        uint4 af[2][4];
#pragma unroll
        for (int mf = 0; mf < 4; mf++) af[0][mf] = Ag[mf * 32];

#pragma unroll
        for (int ks = 0; ks < 8; ks++) {
            // prefetch next ks A frags
            if (ks < 7) {
#pragma unroll
                for (int mf = 0; mf < 4; mf++)
                    af[(ks + 1) & 1][mf] = Ag[((ks + 1) * 8 + mf) * 32];
            }
            uint2 bfr[4];
#pragma unroll
            for (int nf = 0; nf < 4; nf++)
                bfr[nf] = Bs[((wn * 4 + nf) * 8 + ks) * 32 + lane];
#pragma unroll
            for (int mf = 0; mf < 4; mf++) {
                uint4 a = af[ks & 1][mf];
#pragma unroll
                for (int nf = 0; nf < 4; nf++) {
                    asm volatile(
                        "mma.sync.aligned.m16n8k16.row.col.f32.f16.f16.f32 "
                        "{%0,%1,%2,%3}, {%4,%5,%6,%7}, {%8,%9}, {%0,%1,%2,%3};"
                        : "+f"(acc[mf][nf][0]), "+f"(acc[mf][nf][1]),
                          "+f"(acc[mf][nf][2]), "+f"(acc[mf][nf][3])
                        : "r"(a.x), "r"(a.y), "r"(a.z), "r"(a.w),
                          "r"(bfr[nf].x), "r"(bfr[nf].y));
                }
            }
        }

        // ---- fused LSTM epilogue, direct STG.128 (no smem, no barriers) ----
#pragma unroll
        for (int mf = 0; mf < 4; mf++) {
            const int row = wm * 64 + mf * 16 + g + (odd ? 8 : 0);
            const int b = row & 31;
            float hv4[4], cv4[4];
#pragma unroll
            for (int nf = 0; nf < 4; nf++) {
                float c0r = acc[mf][nf][0], c1r = acc[mf][nf][1];
                float c2r = acc[mf][nf][2], c3r = acc[mf][nf][3];
                float v0 = __shfl_xor_sync(0xffffffffu, c0r, 1);
                float v1 = __shfl_xor_sync(0xffffffffu, c1r, 1);
                float v2 = __shfl_xor_sync(0xffffffffu, c2r, 1);
                float v3 = __shfl_xor_sync(0xffffffffu, c3r, 1);
                float g0, g1, g2, g3;
                if (!odd) { g0 = c0r; g1 = c1r; g2 = v0; g3 = v1; }
                else      { g0 = v2;  g1 = v3;  g2 = c2r; g3 = c3r; }
                const int hl = wn * 8 + nf * 2 + th;
                float4 hb = *(float4*)(HBs + b * 132 + hl * 4);
                float gi = g0 + hb.x, gf = g1 + hb.y, gg = g2 + hb.z, go = g3 + hb.w;
                float si = sig_ap(gi), sf = sig_ap(gf), so = sig_ap(go);
                float tg = tanh_ap(gg);
                float cc = sf * C0s[b * 33 + hl] + si * tg;
                float hv = so * tanh_ap(cc) + NZs[b * 33 + hl];
                hv4[nf] = hv; cv4[nf] = cc;
            }
            // gather 4 consecutive head-cols per lane (exchange with lane^2)
            float p0 = __shfl_xor_sync(0xffffffffu, hv4[0], 2);
            float p1 = __shfl_xor_sync(0xffffffffu, hv4[1], 2);
            float p2 = __shfl_xor_sync(0xffffffffu, hv4[2], 2);
            float p3 = __shfl_xor_sync(0xffffffffu, hv4[3], 2);
            float4 f4;
            if (!(t & 2)) f4 = make_float4(hv4[0], p0, hv4[1], p1);   // hl 0..3
            else          f4 = make_float4(p2, hv4[2], p3, hv4[3]);   // hl 4..7
            const long gr = r0 + row;
            *(float4*)(out + gr * 128 + nt * 32 + wn * 8 + (t & 2) * 2) = f4;
            if (gr >= (long)TB_ - 32) {               // last timestep rows
#pragma unroll
                for (int nf = 0; nf < 4; nf++) {
                    const int hl = wn * 8 + nf * 2 + th;
                    long base = (long)TB_ * 128 + (long)b * 128 + nt * 32 + hl;
                    out[base] = hv4[nf];              // h_last
                    out[base + 32 * 128] = cv4[nf];   // c_last
                }
            }
        }
    }
}

// ---------------- launch ----------------
extern "C" void kernel_launch(void* const* d_in, const int* in_sizes, int n_in,
                              void* d_out, int out_size) {
    const float* input = (const float*)d_in[0];
    const float* h0    = (const float*)d_in[1];
    const float* c0    = (const float*)d_in[2];
    const float* noise = (const float*)d_in[3];
    const float* W_ih  = (const float*)d_in[4];
    const float* W_hh  = (const float*)d_in[5];
    const float* b_ih  = (const float*)d_in[6];
    const float* b_hh  = (const float*)d_in[7];
    float* out = (float*)d_out;

    prep_all<<<128 + 8192, 256>>>(input, h0, W_hh, b_ih, b_hh, W_ih);

    cudaFuncSetAttribute(lstm_mma, cudaFuncAttributeMaxDynamicSharedMemorySize, SMEM_TOT);
    lstm_mma<<<1024, 256, SMEM_TOT>>>(c0, noise, out);
}